// round 10
// baseline (speedup 1.0000x reference)
#include <cuda_runtime.h>
#include <cuda_bf16.h>

// Problem constants
//   I     [64, 64, 8192] f32
//   gamma [64], beta [64]
//   W     [128, 64, 7]
//   alpha [128, 1]
//   out   [64, 128, 4096] f32
#define N_  64
#define C_  64
#define L_  8192
#define O_  128
#define K_  7
#define LOUT_ 4096

// Scratch (device globals; no allocations allowed)
__device__ float    g_ps[N_ * C_];          // per-(n,c) partial sum
__device__ float    g_pq[N_ * C_];          // per-(n,c) partial sumsq
__device__ float    g_thresh[C_];           // per-channel binarization threshold
__device__ unsigned g_bits[N_ * C_ * (L_/32)]; // 4 MB packed signs

// ---------------------------------------------------------------------------
// Kernel 1: per-(n,c) row reduction -> partial sum / sumsq
// grid = 4096 (r = n*64 + c), block = 256
// ---------------------------------------------------------------------------
__global__ void k_stats1(const float* __restrict__ I) {
    const int r = blockIdx.x;
    const float4* p = reinterpret_cast<const float4*>(I + (size_t)r * L_);
    float s = 0.f, q = 0.f;
    for (int i = threadIdx.x; i < L_ / 4; i += 256) {
        float4 v = p[i];
        s += v.x + v.y + v.z + v.w;
        q += v.x * v.x + v.y * v.y + v.z * v.z + v.w * v.w;
    }
    // warp reduce
    #pragma unroll
    for (int o = 16; o; o >>= 1) {
        s += __shfl_down_sync(0xFFFFFFFFu, s, o);
        q += __shfl_down_sync(0xFFFFFFFFu, q, o);
    }
    __shared__ float ss[8], sq[8];
    const int w = threadIdx.x >> 5, lane = threadIdx.x & 31;
    if (lane == 0) { ss[w] = s; sq[w] = q; }
    __syncthreads();
    if (w == 0) {
        s = (lane < 8) ? ss[lane] : 0.f;
        q = (lane < 8) ? sq[lane] : 0.f;
        #pragma unroll
        for (int o = 4; o; o >>= 1) {
            s += __shfl_down_sync(0xFFFFFFFFu, s, o);
            q += __shfl_down_sync(0xFFFFFFFFu, q, o);
        }
        if (lane == 0) { g_ps[r] = s; g_pq[r] = q; }
    }
}

// ---------------------------------------------------------------------------
// Kernel 2: finalize stats per channel, compute threshold
//   x = (I - mean)*rsqrt(var+eps)*gamma + beta >= 0
//     <=> I >= mean - beta*sqrt(var+eps)/gamma     (gamma > 0 guaranteed)
// grid = 64 (c), block = 64 (n)
// ---------------------------------------------------------------------------
__global__ void k_stats2(const float* __restrict__ gamma,
                         const float* __restrict__ beta) {
    const int c = blockIdx.x;
    const int n = threadIdx.x;
    float s = g_ps[n * C_ + c];
    float q = g_pq[n * C_ + c];
    #pragma unroll
    for (int o = 16; o; o >>= 1) {
        s += __shfl_down_sync(0xFFFFFFFFu, s, o);
        q += __shfl_down_sync(0xFFFFFFFFu, q, o);
    }
    __shared__ float s1, q1;
    if (threadIdx.x == 32) { s1 = s; q1 = q; }
    __syncthreads();
    if (threadIdx.x == 0) {
        s += s1; q += q1;
        const float invn = 1.f / ((float)N_ * (float)L_);
        float mean = s * invn;
        float var  = fmaf(-mean, mean, q * invn);
        float inv  = rsqrtf(var + 1e-5f);
        g_thresh[c] = mean - beta[c] / (inv * gamma[c]);
    }
}

// ---------------------------------------------------------------------------
// Kernel 3: binarize to packed bits. bit l of word = (I >= thresh)
// grid = 4096 (r = n*64 + c), block = 256 (one 32-bit word per thread)
// ---------------------------------------------------------------------------
__global__ void k_binarize(const float* __restrict__ I) {
    const int r = blockIdx.x;
    const float t = g_thresh[r & (C_ - 1)];
    const float4* p = reinterpret_cast<const float4*>(
        I + (size_t)r * L_ + threadIdx.x * 32);
    unsigned b = 0;
    #pragma unroll
    for (int i = 0; i < 8; i++) {
        float4 v = p[i];
        b |= (v.x >= t ? 1u : 0u) << (i * 4 + 0);
        b |= (v.y >= t ? 1u : 0u) << (i * 4 + 1);
        b |= (v.z >= t ? 1u : 0u) << (i * 4 + 2);
        b |= (v.w >= t ? 1u : 0u) << (i * 4 + 3);
    }
    g_bits[r * (L_ / 32) + threadIdx.x] = b;
}

// ---------------------------------------------------------------------------
// Kernel 4: conv(K=7, pad 3) + alpha scale + maxpool(2)
// grid = (L/128, Cout/32, N); block = 128 threads
// thread = 8 conv positions x 4 out-channels (32 accumulators)
// smem: signs 64x136 f32 (zero for padded positions -> matches zero-pad conv)
//       weights [c][k][32 out-channels] f32
// ---------------------------------------------------------------------------
#define TL 128           // conv positions per block
#define OG 32            // out channels per block
#define SROW 136         // padded sign row (134 used, float4-load safety)

__global__ void __launch_bounds__(128)
k_conv(const float* __restrict__ W,
       const float* __restrict__ alpha,
       float* __restrict__ out) {
    extern __shared__ float sm[];
    float* sm_s = sm;                    // 64 * 136
    float* sm_w = sm + C_ * SROW;        // 64 * 7 * 32, layout [(c*7+k)*32 + ol]

    const int l0  = blockIdx.x * TL;
    const int ogb = blockIdx.y;          // 0..3
    const int n   = blockIdx.z;
    const int tid = threadIdx.x;

    // Load weight tile: contiguous read of W[ogb*32 .. +32) rows, scatter to smem
    {
        const float* Wg = W + (size_t)(ogb * OG) * (C_ * K_);
        for (int i = tid; i < OG * C_ * K_; i += 128) {
            int ol  = i / (C_ * K_);
            int rem = i - ol * (C_ * K_);
            int c   = rem / K_;
            int k   = rem - c * K_;
            sm_w[(c * K_ + k) * OG + ol] = Wg[i];
        }
    }
    // Decode sign tile: sm_s[c][j] = sign at global l = l0 - 3 + j, 0 at pad
    {
        const unsigned* bb = g_bits + (size_t)n * (C_ * (L_ / 32));
        for (int i = tid; i < C_ * SROW; i += 128) {
            int c = i / SROW;
            int j = i - c * SROW;
            int l = l0 - 3 + j;
            float v = 0.f;
            if (l >= 0 && l < L_ && j < 134) {
                unsigned wd = bb[c * (L_ / 32) + (l >> 5)];
                v = ((wd >> (l & 31)) & 1u) ? 1.f : -1.f;
            }
            sm_s[i] = v;
        }
    }
    __syncthreads();

    const int og = tid >> 4;    // 0..7  -> 4 out-channels each
    const int lg = tid & 15;    // 0..15 -> 8 conv positions each
    const int lb = lg * 8;

    float acc[8][4];
    #pragma unroll
    for (int l = 0; l < 8; l++) {
        acc[l][0] = 0.f; acc[l][1] = 0.f; acc[l][2] = 0.f; acc[l][3] = 0.f;
    }

    const float* srow = sm_s + lb;
    const float* wrow = sm_w + og * 4;

    for (int c = 0; c < C_; c++) {
        const float* sc = srow + c * SROW;
        float4 A = *reinterpret_cast<const float4*>(sc);
        float4 B = *reinterpret_cast<const float4*>(sc + 4);
        float4 Cc = *reinterpret_cast<const float4*>(sc + 8);
        float4 D = *reinterpret_cast<const float4*>(sc + 12);
        float sv[16] = {A.x, A.y, A.z, A.w,  B.x, B.y, B.z, B.w,
                        Cc.x, Cc.y, Cc.z, Cc.w,  D.x, D.y, D.z, D.w};
        const float* wc = wrow + c * (K_ * OG);
        #pragma unroll
        for (int k = 0; k < K_; k++) {
            float4 w = *reinterpret_cast<const float4*>(wc + k * OG);
            #pragma unroll
            for (int l = 0; l < 8; l++) {
                float s = sv[l + k];
                acc[l][0] = fmaf(s, w.x, acc[l][0]);
                acc[l][1] = fmaf(s, w.y, acc[l][1]);
                acc[l][2] = fmaf(s, w.z, acc[l][2]);
                acc[l][3] = fmaf(s, w.w, acc[l][3]);
            }
        }
    }

    // Epilogue: alpha (>0) scale + maxpool2, float4 coalesced stores
    const int o0 = ogb * OG + og * 4;
    const float a0 = alpha[o0 + 0];
    const float a1 = alpha[o0 + 1];
    const float a2 = alpha[o0 + 2];
    const float a3 = alpha[o0 + 3];
    const int lp0 = (l0 >> 1) + lg * 4;

    #pragma unroll
    for (int oo = 0; oo < 4; oo++) {
        float av = (oo == 0) ? a0 : (oo == 1) ? a1 : (oo == 2) ? a2 : a3;
        float4 r;
        r.x = fmaxf(acc[0][oo], acc[1][oo]) * av;
        r.y = fmaxf(acc[2][oo], acc[3][oo]) * av;
        r.z = fmaxf(acc[4][oo], acc[5][oo]) * av;
        r.w = fmaxf(acc[6][oo], acc[7][oo]) * av;
        *reinterpret_cast<float4*>(
            out + ((size_t)(n * O_ + o0 + oo)) * LOUT_ + lp0) = r;
    }
}

// ---------------------------------------------------------------------------
extern "C" void kernel_launch(void* const* d_in, const int* in_sizes, int n_in,
                              void* d_out, int out_size) {
    const float* I     = (const float*)d_in[0];
    const float* gamma = (const float*)d_in[1];
    const float* beta  = (const float*)d_in[2];
    const float* W     = (const float*)d_in[3];
    const float* alpha = (const float*)d_in[4];
    float* out = (float*)d_out;

    k_stats1<<<N_ * C_, 256>>>(I);
    k_stats2<<<C_, 64>>>(gamma, beta);
    k_binarize<<<N_ * C_, 256>>>(I);

    const size_t smem = (size_t)(C_ * SROW + C_ * K_ * OG) * sizeof(float); // 92160 B
    cudaFuncSetAttribute(k_conv, cudaFuncAttributeMaxDynamicSharedMemorySize,
                         (int)smem);
    dim3 grid(L_ / TL, O_ / OG, N_);   // (64, 4, 64)
    k_conv<<<grid, 128, smem>>>(W, alpha, out);
}

// round 11
// speedup vs baseline: 1.0009x; 1.0009x over previous
#include <cuda_runtime.h>
#include <cuda_bf16.h>

// Problem constants
//   I     [64, 64, 8192] f32
//   gamma [64], beta [64]
//   W     [128, 64, 7]
//   alpha [128, 1]
//   out   [64, 128, 4096] f32
#define N_  64
#define C_  64
#define L_  8192
#define O_  128
#define K_  7
#define LOUT_ 4096

// Scratch (device globals; no allocations allowed)
__device__ float    g_ps[N_ * C_];          // per-(n,c) partial sum
__device__ float    g_pq[N_ * C_];          // per-(n,c) partial sumsq
__device__ float    g_thresh[C_];           // per-channel binarization threshold
__device__ unsigned g_bits[N_ * C_ * (L_/32)]; // 4 MB packed signs

// ---------------------------------------------------------------------------
// Kernel 1: per-(n,c) row reduction -> partial sum / sumsq
// grid = 4096 (r = n*64 + c), block = 256
// ---------------------------------------------------------------------------
__global__ void k_stats1(const float* __restrict__ I) {
    const int r = blockIdx.x;
    const float4* p = reinterpret_cast<const float4*>(I + (size_t)r * L_);
    float s = 0.f, q = 0.f;
    for (int i = threadIdx.x; i < L_ / 4; i += 256) {
        float4 v = p[i];
        s += v.x + v.y + v.z + v.w;
        q += v.x * v.x + v.y * v.y + v.z * v.z + v.w * v.w;
    }
    // warp reduce
    #pragma unroll
    for (int o = 16; o; o >>= 1) {
        s += __shfl_down_sync(0xFFFFFFFFu, s, o);
        q += __shfl_down_sync(0xFFFFFFFFu, q, o);
    }
    __shared__ float ss[8], sq[8];
    const int w = threadIdx.x >> 5, lane = threadIdx.x & 31;
    if (lane == 0) { ss[w] = s; sq[w] = q; }
    __syncthreads();
    if (w == 0) {
        s = (lane < 8) ? ss[lane] : 0.f;
        q = (lane < 8) ? sq[lane] : 0.f;
        #pragma unroll
        for (int o = 4; o; o >>= 1) {
            s += __shfl_down_sync(0xFFFFFFFFu, s, o);
            q += __shfl_down_sync(0xFFFFFFFFu, q, o);
        }
        if (lane == 0) { g_ps[r] = s; g_pq[r] = q; }
    }
}

// ---------------------------------------------------------------------------
// Kernel 2: finalize stats per channel, compute threshold
//   x = (I - mean)*rsqrt(var+eps)*gamma + beta >= 0
//     <=> I >= mean - beta*sqrt(var+eps)/gamma     (gamma > 0 guaranteed)
// grid = 64 (c), block = 64 (n)
// ---------------------------------------------------------------------------
__global__ void k_stats2(const float* __restrict__ gamma,
                         const float* __restrict__ beta) {
    const int c = blockIdx.x;
    const int n = threadIdx.x;
    float s = g_ps[n * C_ + c];
    float q = g_pq[n * C_ + c];
    #pragma unroll
    for (int o = 16; o; o >>= 1) {
        s += __shfl_down_sync(0xFFFFFFFFu, s, o);
        q += __shfl_down_sync(0xFFFFFFFFu, q, o);
    }
    __shared__ float s1, q1;
    if (threadIdx.x == 32) { s1 = s; q1 = q; }
    __syncthreads();
    if (threadIdx.x == 0) {
        s += s1; q += q1;
        const float invn = 1.f / ((float)N_ * (float)L_);
        float mean = s * invn;
        float var  = fmaf(-mean, mean, q * invn);
        float inv  = rsqrtf(var + 1e-5f);
        g_thresh[c] = mean - beta[c] / (inv * gamma[c]);
    }
}

// ---------------------------------------------------------------------------
// Kernel 3: binarize to packed bits. bit l of word = (I >= thresh)
// grid = 4096 (r = n*64 + c), block = 256 (one 32-bit word per thread)
// ---------------------------------------------------------------------------
__global__ void k_binarize(const float* __restrict__ I) {
    const int r = blockIdx.x;
    const float t = g_thresh[r & (C_ - 1)];
    const float4* p = reinterpret_cast<const float4*>(
        I + (size_t)r * L_ + threadIdx.x * 32);
    unsigned b = 0;
    #pragma unroll
    for (int i = 0; i < 8; i++) {
        float4 v = p[i];
        b |= (v.x >= t ? 1u : 0u) << (i * 4 + 0);
        b |= (v.y >= t ? 1u : 0u) << (i * 4 + 1);
        b |= (v.z >= t ? 1u : 0u) << (i * 4 + 2);
        b |= (v.w >= t ? 1u : 0u) << (i * 4 + 3);
    }
    g_bits[r * (L_ / 32) + threadIdx.x] = b;
}

// ---------------------------------------------------------------------------
// Kernel 4: conv(K=7, pad 3) + alpha scale + maxpool(2)
// grid = (L/128, Cout/32, N); block = 128 threads
// thread = 8 conv positions x 4 out-channels (32 accumulators)
// smem: signs 64x136 f32 (zero for padded positions -> matches zero-pad conv)
//       weights [c][k][32 out-channels] f32
// ---------------------------------------------------------------------------
#define TL 128           // conv positions per block
#define OG 32            // out channels per block
#define SROW 136         // padded sign row (134 used, float4-load safety)

__global__ void __launch_bounds__(128)
k_conv(const float* __restrict__ W,
       const float* __restrict__ alpha,
       float* __restrict__ out) {
    extern __shared__ float sm[];
    float* sm_s = sm;                    // 64 * 136
    float* sm_w = sm + C_ * SROW;        // 64 * 7 * 32, layout [(c*7+k)*32 + ol]

    const int l0  = blockIdx.x * TL;
    const int ogb = blockIdx.y;          // 0..3
    const int n   = blockIdx.z;
    const int tid = threadIdx.x;

    // Load weight tile: contiguous read of W[ogb*32 .. +32) rows, scatter to smem
    {
        const float* Wg = W + (size_t)(ogb * OG) * (C_ * K_);
        for (int i = tid; i < OG * C_ * K_; i += 128) {
            int ol  = i / (C_ * K_);
            int rem = i - ol * (C_ * K_);
            int c   = rem / K_;
            int k   = rem - c * K_;
            sm_w[(c * K_ + k) * OG + ol] = Wg[i];
        }
    }
    // Decode sign tile: sm_s[c][j] = sign at global l = l0 - 3 + j, 0 at pad
    {
        const unsigned* bb = g_bits + (size_t)n * (C_ * (L_ / 32));
        for (int i = tid; i < C_ * SROW; i += 128) {
            int c = i / SROW;
            int j = i - c * SROW;
            int l = l0 - 3 + j;
            float v = 0.f;
            if (l >= 0 && l < L_ && j < 134) {
                unsigned wd = bb[c * (L_ / 32) + (l >> 5)];
                v = ((wd >> (l & 31)) & 1u) ? 1.f : -1.f;
            }
            sm_s[i] = v;
        }
    }
    __syncthreads();

    const int og = tid >> 4;    // 0..7  -> 4 out-channels each
    const int lg = tid & 15;    // 0..15 -> 8 conv positions each
    const int lb = lg * 8;

    float acc[8][4];
    #pragma unroll
    for (int l = 0; l < 8; l++) {
        acc[l][0] = 0.f; acc[l][1] = 0.f; acc[l][2] = 0.f; acc[l][3] = 0.f;
    }

    const float* srow = sm_s + lb;
    const float* wrow = sm_w + og * 4;

    for (int c = 0; c < C_; c++) {
        const float* sc = srow + c * SROW;
        float4 A = *reinterpret_cast<const float4*>(sc);
        float4 B = *reinterpret_cast<const float4*>(sc + 4);
        float4 Cc = *reinterpret_cast<const float4*>(sc + 8);
        float4 D = *reinterpret_cast<const float4*>(sc + 12);
        float sv[16] = {A.x, A.y, A.z, A.w,  B.x, B.y, B.z, B.w,
                        Cc.x, Cc.y, Cc.z, Cc.w,  D.x, D.y, D.z, D.w};
        const float* wc = wrow + c * (K_ * OG);
        #pragma unroll
        for (int k = 0; k < K_; k++) {
            float4 w = *reinterpret_cast<const float4*>(wc + k * OG);
            #pragma unroll
            for (int l = 0; l < 8; l++) {
                float s = sv[l + k];
                acc[l][0] = fmaf(s, w.x, acc[l][0]);
                acc[l][1] = fmaf(s, w.y, acc[l][1]);
                acc[l][2] = fmaf(s, w.z, acc[l][2]);
                acc[l][3] = fmaf(s, w.w, acc[l][3]);
            }
        }
    }

    // Epilogue: alpha (>0) scale + maxpool2, float4 coalesced stores
    const int o0 = ogb * OG + og * 4;
    const float a0 = alpha[o0 + 0];
    const float a1 = alpha[o0 + 1];
    const float a2 = alpha[o0 + 2];
    const float a3 = alpha[o0 + 3];
    const int lp0 = (l0 >> 1) + lg * 4;

    #pragma unroll
    for (int oo = 0; oo < 4; oo++) {
        float av = (oo == 0) ? a0 : (oo == 1) ? a1 : (oo == 2) ? a2 : a3;
        float4 r;
        r.x = fmaxf(acc[0][oo], acc[1][oo]) * av;
        r.y = fmaxf(acc[2][oo], acc[3][oo]) * av;
        r.z = fmaxf(acc[4][oo], acc[5][oo]) * av;
        r.w = fmaxf(acc[6][oo], acc[7][oo]) * av;
        *reinterpret_cast<float4*>(
            out + ((size_t)(n * O_ + o0 + oo)) * LOUT_ + lp0) = r;
    }
}

// ---------------------------------------------------------------------------
extern "C" void kernel_launch(void* const* d_in, const int* in_sizes, int n_in,
                              void* d_out, int out_size) {
    const float* I     = (const float*)d_in[0];
    const float* gamma = (const float*)d_in[1];
    const float* beta  = (const float*)d_in[2];
    const float* W     = (const float*)d_in[3];
    const float* alpha = (const float*)d_in[4];
    float* out = (float*)d_out;

    k_stats1<<<N_ * C_, 256>>>(I);
    k_stats2<<<C_, 64>>>(gamma, beta);
    k_binarize<<<N_ * C_, 256>>>(I);

    const size_t smem = (size_t)(C_ * SROW + C_ * K_ * OG) * sizeof(float); // 92160 B
    cudaFuncSetAttribute(k_conv, cudaFuncAttributeMaxDynamicSharedMemorySize,
                         (int)smem);
    dim3 grid(L_ / TL, O_ / OG, N_);   // (64, 4, 64)
    k_conv<<<grid, 128, smem>>>(W, alpha, out);
}

// round 12
// speedup vs baseline: 1.3563x; 1.3551x over previous
#include <cuda_runtime.h>
#include <cuda_bf16.h>

// Problem constants
//   I     [64, 64, 8192] f32
//   gamma [64], beta [64]
//   W     [128, 64, 7]
//   alpha [128, 1]
//   out   [64, 128, 4096] f32
#define N_  64
#define C_  64
#define L_  8192
#define O_  128
#define K_  7
#define LOUT_ 4096

// Scratch (device globals; no allocations allowed)
__device__ float    g_ps[N_ * C_];
__device__ float    g_pq[N_ * C_];
__device__ float    g_thresh[C_];
__device__ unsigned g_bits[N_ * C_ * (L_/32)];   // 4 MB packed signs

// ---------------- packed f32x2 helpers (Blackwell FFMA2) -------------------
__device__ __forceinline__ void fma2(unsigned long long& d,
                                     unsigned long long a,
                                     unsigned long long b) {
    asm("fma.rn.f32x2 %0, %1, %2, %0;" : "+l"(d) : "l"(a), "l"(b));
}
__device__ __forceinline__ unsigned long long pack2(float s) {
    unsigned long long d;
    asm("mov.b64 %0, {%1, %1};" : "=l"(d) : "f"(s));
    return d;
}
__device__ __forceinline__ void unpack2(unsigned long long v, float& lo, float& hi) {
    asm("mov.b64 {%0, %1}, %2;" : "=f"(lo), "=f"(hi) : "l"(v));
}

// ---------------------------------------------------------------------------
// Kernel 1: per-(n,c) row reduction -> partial sum / sumsq
// ---------------------------------------------------------------------------
__global__ void k_stats1(const float* __restrict__ I) {
    const int r = blockIdx.x;
    const float4* p = reinterpret_cast<const float4*>(I + (size_t)r * L_);
    float s = 0.f, q = 0.f;
    for (int i = threadIdx.x; i < L_ / 4; i += 256) {
        float4 v = p[i];
        s += v.x + v.y + v.z + v.w;
        q += v.x * v.x + v.y * v.y + v.z * v.z + v.w * v.w;
    }
    #pragma unroll
    for (int o = 16; o; o >>= 1) {
        s += __shfl_down_sync(0xFFFFFFFFu, s, o);
        q += __shfl_down_sync(0xFFFFFFFFu, q, o);
    }
    __shared__ float ss[8], sq[8];
    const int w = threadIdx.x >> 5, lane = threadIdx.x & 31;
    if (lane == 0) { ss[w] = s; sq[w] = q; }
    __syncthreads();
    if (w == 0) {
        s = (lane < 8) ? ss[lane] : 0.f;
        q = (lane < 8) ? sq[lane] : 0.f;
        #pragma unroll
        for (int o = 4; o; o >>= 1) {
            s += __shfl_down_sync(0xFFFFFFFFu, s, o);
            q += __shfl_down_sync(0xFFFFFFFFu, q, o);
        }
        if (lane == 0) { g_ps[r] = s; g_pq[r] = q; }
    }
}

// ---------------------------------------------------------------------------
// Kernel 2: finalize stats, per-channel threshold (gamma > 0 guaranteed)
// ---------------------------------------------------------------------------
__global__ void k_stats2(const float* __restrict__ gamma,
                         const float* __restrict__ beta) {
    const int c = blockIdx.x;
    const int n = threadIdx.x;
    float s = g_ps[n * C_ + c];
    float q = g_pq[n * C_ + c];
    #pragma unroll
    for (int o = 16; o; o >>= 1) {
        s += __shfl_down_sync(0xFFFFFFFFu, s, o);
        q += __shfl_down_sync(0xFFFFFFFFu, q, o);
    }
    __shared__ float s1, q1;
    if (threadIdx.x == 32) { s1 = s; q1 = q; }
    __syncthreads();
    if (threadIdx.x == 0) {
        s += s1; q += q1;
        const float invn = 1.f / ((float)N_ * (float)L_);
        float mean = s * invn;
        float var  = fmaf(-mean, mean, q * invn);
        float inv  = rsqrtf(var + 1e-5f);
        g_thresh[c] = mean - beta[c] / (inv * gamma[c]);
    }
}

// ---------------------------------------------------------------------------
// Kernel 3: binarize to packed bits
// ---------------------------------------------------------------------------
__global__ void k_binarize(const float* __restrict__ I) {
    const int r = blockIdx.x;
    const float t = g_thresh[r & (C_ - 1)];
    const float4* p = reinterpret_cast<const float4*>(
        I + (size_t)r * L_ + threadIdx.x * 32);
    unsigned b = 0;
    #pragma unroll
    for (int i = 0; i < 8; i++) {
        float4 v = p[i];
        b |= (v.x >= t ? 1u : 0u) << (i * 4 + 0);
        b |= (v.y >= t ? 1u : 0u) << (i * 4 + 1);
        b |= (v.z >= t ? 1u : 0u) << (i * 4 + 2);
        b |= (v.w >= t ? 1u : 0u) << (i * 4 + 3);
    }
    g_bits[r * (L_ / 32) + threadIdx.x] = b;
}

// ---------------------------------------------------------------------------
// Kernel 4: conv(K=7,pad3) + alpha + maxpool2, packed f32x2 math
// grid=(64,4,64) block=128; tile = 128 pos x 32 oc; thread = 8 pos x 4 oc
// smem: signs [64][136] f32, weights [448][34] f32 ([(c*7+k)*34 + ol], +2 pad)
// ---------------------------------------------------------------------------
#define TL   128
#define OG   32
#define SROW 136
#define WROW 34

__global__ void __launch_bounds__(128)
k_conv(const float* __restrict__ W,
       const float* __restrict__ alpha,
       float* __restrict__ out) {
    extern __shared__ float sm[];
    float* sm_s = sm;                    // 64 * 136  (8704 floats)
    float* sm_w = sm + C_ * SROW;        // 448 * 34  (15232 floats)

    const int l0  = blockIdx.x * TL;
    const int ogb = blockIdx.y;
    const int n   = blockIdx.z;
    const int tid = threadIdx.x;

    // --- weights: global [ol][c][k] (contiguous per ol) -> sm_w[(c*7+k)*34+ol]
    {
        const float4* Wg4 = reinterpret_cast<const float4*>(
            W + (size_t)(ogb * OG) * (C_ * K_));
        for (int i = tid; i < OG * C_ * K_ / 4; i += 128) {  // 3584 float4s
            float4 v = Wg4[i];
            int e  = i * 4;
            int ol = e / (C_ * K_);
            int r  = e - ol * (C_ * K_);   // r..r+3 share ol (448 % 4 == 0)
            sm_w[(r + 0) * WROW + ol] = v.x;
            sm_w[(r + 1) * WROW + ol] = v.y;
            sm_w[(r + 2) * WROW + ol] = v.z;
            sm_w[(r + 3) * WROW + ol] = v.w;
        }
    }
    // --- signs: 2 threads per channel, sm_s[c][j] = sign(l0-3+j), 0 at pad
    {
        const int c = tid >> 1, half = tid & 1;
        const unsigned* bw = g_bits + ((size_t)n * C_ + c) * (L_ / 32);
        float* srow = sm_s + c * SROW;
        const int j0 = half * 68;
        for (int j = j0; j < j0 + 68; j++) {
            int l = l0 - 3 + j;
            float v = 0.f;
            if (l >= 0 && l < L_ && j < 134)
                v = ((bw[l >> 5] >> (l & 31)) & 1u) ? 1.f : -1.f;
            srow[j] = v;
        }
    }
    __syncthreads();

    const int pg  = tid >> 3;   // 0..15, 8 positions each
    const int ocg = tid & 7;    // 0..7,  4 out-channels each (2 b64 pairs)
    const int lb  = pg * 8;

    unsigned long long acc[8][2];
    #pragma unroll
    for (int i = 0; i < 8; i++) { acc[i][0] = 0ull; acc[i][1] = 0ull; }

    const float* sbase = sm_s + lb;
    const float* wbase = sm_w + ocg * 4;

    #pragma unroll 1
    for (int c = 0; c < C_; c++) {
        const float4* sp = reinterpret_cast<const float4*>(sbase + c * SROW);
        float4 A = sp[0], B = sp[1], Cc = sp[2], D = sp[3];
        float s[16] = {A.x, A.y, A.z, A.w,  B.x, B.y, B.z, B.w,
                       Cc.x, Cc.y, Cc.z, Cc.w,  D.x, D.y, D.z, D.w};
        unsigned long long ssd[14];
        #pragma unroll
        for (int j = 0; j < 14; j++) ssd[j] = pack2(s[j]);

        const float* wc = wbase + c * (K_ * WROW);
        #pragma unroll
        for (int k = 0; k < K_; k++) {
            unsigned long long wa =
                *reinterpret_cast<const unsigned long long*>(wc + k * WROW);
            unsigned long long wb =
                *reinterpret_cast<const unsigned long long*>(wc + k * WROW + 2);
            #pragma unroll
            for (int i = 0; i < 8; i++) {
                fma2(acc[i][0], ssd[i + k], wa);
                fma2(acc[i][1], ssd[i + k], wb);
            }
        }
    }

    // --- epilogue: unpack, maxpool2, alpha (>0) scale, float4 stores
    float f[8][4];
    #pragma unroll
    for (int i = 0; i < 8; i++) {
        unpack2(acc[i][0], f[i][0], f[i][1]);
        unpack2(acc[i][1], f[i][2], f[i][3]);
    }
    const int o0 = ogb * OG + ocg * 4;
    float4 a4 = *reinterpret_cast<const float4*>(alpha + o0);
    const float av[4] = {a4.x, a4.y, a4.z, a4.w};
    const int lp0 = (l0 >> 1) + pg * 4;

    #pragma unroll
    for (int oo = 0; oo < 4; oo++) {
        float4 r;
        r.x = fmaxf(f[0][oo], f[1][oo]) * av[oo];
        r.y = fmaxf(f[2][oo], f[3][oo]) * av[oo];
        r.z = fmaxf(f[4][oo], f[5][oo]) * av[oo];
        r.w = fmaxf(f[6][oo], f[7][oo]) * av[oo];
        *reinterpret_cast<float4*>(
            out + ((size_t)(n * O_ + o0 + oo)) * LOUT_ + lp0) = r;
    }
}

// ---------------------------------------------------------------------------
extern "C" void kernel_launch(void* const* d_in, const int* in_sizes, int n_in,
                              void* d_out, int out_size) {
    const float* I     = (const float*)d_in[0];
    const float* gamma = (const float*)d_in[1];
    const float* beta  = (const float*)d_in[2];
    const float* W     = (const float*)d_in[3];
    const float* alpha = (const float*)d_in[4];
    float* out = (float*)d_out;

    k_stats1<<<N_ * C_, 256>>>(I);
    k_stats2<<<C_, 64>>>(gamma, beta);
    k_binarize<<<N_ * C_, 256>>>(I);

    const size_t smem = (size_t)(C_ * SROW + C_ * K_ * WROW) * sizeof(float); // 95744 B
    cudaFuncSetAttribute(k_conv, cudaFuncAttributeMaxDynamicSharedMemorySize,
                         (int)smem);
    dim3 grid(L_ / TL, O_ / OG, N_);   // (64, 4, 64)
    k_conv<<<grid, 128, smem>>>(W, alpha, out);
}

// round 14
// speedup vs baseline: 6.6809x; 4.9260x over previous
#include <cuda_runtime.h>
#include <cuda_fp16.h>
#include <cstdint>

// Problem constants
//   I     [64, 64, 8192] f32
//   gamma [64], beta [64]
//   W     [128, 64, 7]
//   alpha [128, 1]
//   out   [64, 128, 4096] f32
#define N_  64
#define C_  64
#define L_  8192
#define O_  128
#define K_  7
#define LOUT_ 4096

// Scratch (device globals; no allocations allowed)
__device__ float    g_ps[N_ * C_];
__device__ float    g_pq[N_ * C_];
__device__ float    g_thresh[C_];
__device__ unsigned g_bits[N_ * C_ * (L_/32) + 16];

// ====================== baseline-PTX warp MMA helpers ======================
__device__ __forceinline__ uint32_t smem_u32(const void* p) {
    uint32_t a;
    asm("{ .reg .u64 t; cvta.to.shared.u64 t, %1; cvt.u32.u64 %0, t; }"
        : "=r"(a) : "l"(p));
    return a;
}
__device__ __forceinline__ void ldsm_x4(uint32_t* r, uint32_t addr) {
    asm volatile("ldmatrix.sync.aligned.m8n8.x4.shared.b16 {%0,%1,%2,%3}, [%4];"
                 : "=r"(r[0]), "=r"(r[1]), "=r"(r[2]), "=r"(r[3]) : "r"(addr));
}
__device__ __forceinline__ void ldsm_x2(uint32_t* r, uint32_t addr) {
    asm volatile("ldmatrix.sync.aligned.m8n8.x2.shared.b16 {%0,%1}, [%2];"
                 : "=r"(r[0]), "=r"(r[1]) : "r"(addr));
}
__device__ __forceinline__ void mma16816(float* d, const uint32_t* a,
                                         const uint32_t* b) {
    asm volatile(
        "mma.sync.aligned.m16n8k16.row.col.f32.f16.f16.f32 "
        "{%0,%1,%2,%3}, {%4,%5,%6,%7}, {%8,%9}, {%0,%1,%2,%3};"
        : "+f"(d[0]), "+f"(d[1]), "+f"(d[2]), "+f"(d[3])
        : "r"(a[0]), "r"(a[1]), "r"(a[2]), "r"(a[3]), "r"(b[0]), "r"(b[1]));
}

// ---------------------------------------------------------------------------
// Kernel 1: per-(n,c) row reduction
// ---------------------------------------------------------------------------
__global__ void k_stats1(const float* __restrict__ I) {
    const int r = blockIdx.x;
    const float4* p = reinterpret_cast<const float4*>(I + (size_t)r * L_);
    float s = 0.f, q = 0.f;
    for (int i = threadIdx.x; i < L_ / 4; i += 256) {
        float4 v = p[i];
        s += v.x + v.y + v.z + v.w;
        q += v.x * v.x + v.y * v.y + v.z * v.z + v.w * v.w;
    }
    #pragma unroll
    for (int o = 16; o; o >>= 1) {
        s += __shfl_down_sync(0xFFFFFFFFu, s, o);
        q += __shfl_down_sync(0xFFFFFFFFu, q, o);
    }
    __shared__ float ss[8], sq[8];
    const int w = threadIdx.x >> 5, lane = threadIdx.x & 31;
    if (lane == 0) { ss[w] = s; sq[w] = q; }
    __syncthreads();
    if (w == 0) {
        s = (lane < 8) ? ss[lane] : 0.f;
        q = (lane < 8) ? sq[lane] : 0.f;
        #pragma unroll
        for (int o = 4; o; o >>= 1) {
            s += __shfl_down_sync(0xFFFFFFFFu, s, o);
            q += __shfl_down_sync(0xFFFFFFFFu, q, o);
        }
        if (lane == 0) { g_ps[r] = s; g_pq[r] = q; }
    }
}

// ---------------------------------------------------------------------------
// Kernel 2: per-channel threshold (gamma > 0 guaranteed)
// ---------------------------------------------------------------------------
__global__ void k_stats2(const float* __restrict__ gamma,
                         const float* __restrict__ beta) {
    const int c = blockIdx.x;
    const int n = threadIdx.x;
    float s = g_ps[n * C_ + c];
    float q = g_pq[n * C_ + c];
    #pragma unroll
    for (int o = 16; o; o >>= 1) {
        s += __shfl_down_sync(0xFFFFFFFFu, s, o);
        q += __shfl_down_sync(0xFFFFFFFFu, q, o);
    }
    __shared__ float s1, q1;
    if (threadIdx.x == 32) { s1 = s; q1 = q; }
    __syncthreads();
    if (threadIdx.x == 0) {
        s += s1; q += q1;
        const float invn = 1.f / ((float)N_ * (float)L_);
        float mean = s * invn;
        float var  = fmaf(-mean, mean, q * invn);
        float inv  = rsqrtf(var + 1e-5f);
        g_thresh[c] = mean - beta[c] / (inv * gamma[c]);
    }
}

// ---------------------------------------------------------------------------
// Kernel 3: binarize to packed bits
// ---------------------------------------------------------------------------
__global__ void k_binarize(const float* __restrict__ I) {
    const int r = blockIdx.x;
    const float t = g_thresh[r & (C_ - 1)];
    const float4* p = reinterpret_cast<const float4*>(
        I + (size_t)r * L_ + threadIdx.x * 32);
    unsigned b = 0;
    #pragma unroll
    for (int i = 0; i < 8; i++) {
        float4 v = p[i];
        b |= (v.x >= t ? 1u : 0u) << (i * 4 + 0);
        b |= (v.y >= t ? 1u : 0u) << (i * 4 + 1);
        b |= (v.z >= t ? 1u : 0u) << (i * 4 + 2);
        b |= (v.w >= t ? 1u : 0u) << (i * 4 + 3);
    }
    g_bits[r * (L_ / 32) + threadIdx.x] = b;
}

// ---------------------------------------------------------------------------
// Kernel 4: HMMA conv (7 shifted GEMM passes) + alpha + maxpool2
// grid = (32 pos-tiles, 64 n), block = 512 (16 warps)
// Block out tile: [128 oc x 256 pos]; warp tile 64 oc x 32 pos.
// smem:
//   A_k [128 oc][64 c] fp16, k=0..6, pitch 144B  @ 0       (7 * 18432)
//   B^T [262 rows][64 c] fp16, pitch 144B        @ 129024  (37728)
//   row r of B^T = signs at position l0 - 3 + r (0 outside [0,L))
// For tap k: D[oc][n] += A_k[oc][:] . B^T[n + k][:]   (row shift only,
// so every ldmatrix address stays 16B-aligned)
// D frag: d0/d1 (d2/d3) are adjacent positions in one thread -> maxpool+alpha
// happen in registers before STG.
// ---------------------------------------------------------------------------
#define PT     256
#define APITCH 144
#define AK_SZ  (128 * APITCH)          // 18432
#define SM_B   (7 * AK_SZ)             // 129024
#define SM_TOT (SM_B + 262 * APITCH)   // 166752

__global__ void __launch_bounds__(512, 1)
k_conv_mma(const float* __restrict__ W,
           const float* __restrict__ alpha,
           float* __restrict__ out) {
    extern __shared__ char sm[];
    const uint32_t smb = smem_u32(sm);
    const int tid  = threadIdx.x;
    const int wid  = tid >> 5;
    const int lane = tid & 31;
    const int l0 = blockIdx.x * PT;
    const int n  = blockIdx.y;

    // --- decode A: W[oc][c][k] f32 -> A_k[oc][c] fp16
    {
        const float4* Wg = reinterpret_cast<const float4*>(W);
        for (int i = tid; i < (O_ * C_ * K_) / 4; i += 512) {   // 14336
            float4 v = Wg[i];
            int e  = i * 4;
            int oc = e / (C_ * K_);
            int r  = e - oc * (C_ * K_);        // r..r+3 same oc (448%4==0)
            float f[4] = {v.x, v.y, v.z, v.w};
            #pragma unroll
            for (int j = 0; j < 4; j++) {
                int cc = (r + j) / K_;
                int kk = (r + j) - cc * K_;
                *reinterpret_cast<__half*>(
                    sm + kk * AK_SZ + oc * APITCH + cc * 2) =
                    __float2half_rn(f[j]);
            }
        }
    }
    // --- decode B^T: row r = position l0-3+r, 64 channels, fp16
    {
        const unsigned* bb = g_bits + (size_t)n * (C_ * (L_ / 32));
        for (int r = tid; r < 262; r += 512) {
            const int pos = l0 - 3 + r;
            char* row = sm + SM_B + r * APITCH;
            if (pos >= 0 && pos < L_) {
                const int widx = pos >> 5, bit = pos & 31;
                #pragma unroll
                for (int g = 0; g < 8; g++) {           // 8 channels / STS.128
                    uint32_t h4[4];
                    #pragma unroll
                    for (int j = 0; j < 4; j++) {
                        int c0 = g * 8 + j * 2;
                        unsigned w0 = bb[(c0 + 0) * (L_ / 32) + widx];
                        unsigned w1 = bb[(c0 + 1) * (L_ / 32) + widx];
                        uint32_t hlo = ((w0 >> bit) & 1u) ? 0x3C00u : 0xBC00u;
                        uint32_t hhi = ((w1 >> bit) & 1u) ? 0x3C00u : 0xBC00u;
                        h4[j] = hlo | (hhi << 16);
                    }
                    uint4 v; v.x = h4[0]; v.y = h4[1]; v.z = h4[2]; v.w = h4[3];
                    *reinterpret_cast<uint4*>(row + g * 16) = v;
                }
            } else {
                #pragma unroll
                for (int g = 0; g < 8; g++) {
                    uint4 z; z.x = z.y = z.z = z.w = 0u;
                    *reinterpret_cast<uint4*>(row + g * 16) = z;
                }
            }
        }
    }
    __syncthreads();

    // --- mainloop
    const int ocw = (wid & 1) * 64;        // warp oc base
    const int n0w = (wid >> 1) * 32;       // warp pos base

    float acc[4][4][4];                    // [mi][ni][frag]
    #pragma unroll
    for (int mi = 0; mi < 4; mi++)
        #pragma unroll
        for (int ni = 0; ni < 4; ni++)
            #pragma unroll
            for (int j = 0; j < 4; j++) acc[mi][ni][j] = 0.f;

    const uint32_t a_lane = (uint32_t)((lane & 15) * APITCH + (lane >> 4) * 16);
    const uint32_t b_lane = (uint32_t)((lane & 7)  * APITCH + ((lane >> 3) & 1) * 16);
    const uint32_t a_base = smb + ocw * APITCH + a_lane;
    const uint32_t b_base = smb + SM_B + n0w * APITCH + b_lane;

    #pragma unroll 1
    for (int k = 0; k < K_; k++) {
        const uint32_t ab = a_base + k * AK_SZ;
        const uint32_t bbk = b_base + k * APITCH;   // tap shift = +1 row
        #pragma unroll
        for (int ks = 0; ks < 4; ks++) {            // c in steps of 16
            uint32_t a[4][4];
            #pragma unroll
            for (int mi = 0; mi < 4; mi++)
                ldsm_x4(a[mi], ab + mi * (16 * APITCH) + ks * 32);
            uint32_t b[4][2];
            #pragma unroll
            for (int ni = 0; ni < 4; ni++)
                ldsm_x2(b[ni], bbk + ni * (8 * APITCH) + ks * 32);
            #pragma unroll
            for (int mi = 0; mi < 4; mi++)
                #pragma unroll
                for (int ni = 0; ni < 4; ni++)
                    mma16816(acc[mi][ni], a[mi], b[ni]);
        }
    }

    // --- epilogue: maxpool2 + alpha in registers, direct STG
    const int lr = lane >> 2;     // 0..7
    const int lc = lane & 3;      // 0..3
    const int pbase = (l0 >> 1) + (n0w >> 1);
    #pragma unroll
    for (int mi = 0; mi < 4; mi++) {
        const int oc0 = ocw + mi * 16 + lr;
        const int oc1 = oc0 + 8;
        const float a0 = alpha[oc0];
        const float a1 = alpha[oc1];
        float* r0 = out + ((size_t)(n * O_ + oc0)) * LOUT_ + pbase;
        float* r1 = out + ((size_t)(n * O_ + oc1)) * LOUT_ + pbase;
        #pragma unroll
        for (int ni = 0; ni < 4; ni++) {
            const int pp = ni * 4 + lc;
            r0[pp] = fmaxf(acc[mi][ni][0], acc[mi][ni][1]) * a0;
            r1[pp] = fmaxf(acc[mi][ni][2], acc[mi][ni][3]) * a1;
        }
    }
}

// ---------------------------------------------------------------------------
extern "C" void kernel_launch(void* const* d_in, const int* in_sizes, int n_in,
                              void* d_out, int out_size) {
    const float* I     = (const float*)d_in[0];
    const float* gamma = (const float*)d_in[1];
    const float* beta  = (const float*)d_in[2];
    const float* W     = (const float*)d_in[3];
    const float* alpha = (const float*)d_in[4];
    float* out = (float*)d_out;

    k_stats1<<<N_ * C_, 256>>>(I);
    k_stats2<<<C_, 64>>>(gamma, beta);
    k_binarize<<<N_ * C_, 256>>>(I);

    cudaFuncSetAttribute(k_conv_mma,
                         cudaFuncAttributeMaxDynamicSharedMemorySize, SM_TOT);
    dim3 grid(L_ / PT, N_);   // (32, 64)
    k_conv_mma<<<grid, 512, SM_TOT>>>(W, alpha, out);
}

// round 15
// speedup vs baseline: 7.4580x; 1.1163x over previous
#include <cuda_runtime.h>
#include <cuda_fp16.h>
#include <cstdint>

// Problem constants
//   I     [64, 64, 8192] f32
//   gamma [64], beta [64]
//   W     [128, 64, 7]
//   alpha [128, 1]
//   out   [64, 128, 4096] f32
#define N_  64
#define C_  64
#define L_  8192
#define O_  128
#define K_  7
#define LOUT_ 4096
#define LW_  256          // words per (n,c) row = L/32

// Scratch (device globals; no allocations allowed)
__device__ float    g_ps[N_ * C_];
__device__ float    g_pq[N_ * C_];
__device__ float    g_thresh[C_];
// bits transposed: [n][word w][channel c]  (word w covers positions 32w..32w+31)
__device__ unsigned g_bits[N_ * LW_ * C_ + 16];
// fp16 weights: [k][oc][c]
__device__ __align__(16) __half g_wf16[K_ * O_ * C_];

// ====================== baseline-PTX warp MMA helpers ======================
__device__ __forceinline__ uint32_t smem_u32(const void* p) {
    uint32_t a;
    asm("{ .reg .u64 t; cvta.to.shared.u64 t, %1; cvt.u32.u64 %0, t; }"
        : "=r"(a) : "l"(p));
    return a;
}
__device__ __forceinline__ void ldsm_x4(uint32_t* r, uint32_t addr) {
    asm volatile("ldmatrix.sync.aligned.m8n8.x4.shared.b16 {%0,%1,%2,%3}, [%4];"
                 : "=r"(r[0]), "=r"(r[1]), "=r"(r[2]), "=r"(r[3]) : "r"(addr));
}
__device__ __forceinline__ void ldsm_x2(uint32_t* r, uint32_t addr) {
    asm volatile("ldmatrix.sync.aligned.m8n8.x2.shared.b16 {%0,%1}, [%2];"
                 : "=r"(r[0]), "=r"(r[1]) : "r"(addr));
}
__device__ __forceinline__ void mma16816(float* d, const uint32_t* a,
                                         const uint32_t* b) {
    asm volatile(
        "mma.sync.aligned.m16n8k16.row.col.f32.f16.f16.f32 "
        "{%0,%1,%2,%3}, {%4,%5,%6,%7}, {%8,%9}, {%0,%1,%2,%3};"
        : "+f"(d[0]), "+f"(d[1]), "+f"(d[2]), "+f"(d[3])
        : "r"(a[0]), "r"(a[1]), "r"(a[2]), "r"(a[3]), "r"(b[0]), "r"(b[1]));
}

// ---------------------------------------------------------------------------
// Kernel 1: per-(n,c) row reduction
// ---------------------------------------------------------------------------
__global__ void k_stats1(const float* __restrict__ I) {
    const int r = blockIdx.x;
    const float4* p = reinterpret_cast<const float4*>(I + (size_t)r * L_);
    float s = 0.f, q = 0.f;
    for (int i = threadIdx.x; i < L_ / 4; i += 256) {
        float4 v = p[i];
        s += v.x + v.y + v.z + v.w;
        q += v.x * v.x + v.y * v.y + v.z * v.z + v.w * v.w;
    }
    #pragma unroll
    for (int o = 16; o; o >>= 1) {
        s += __shfl_down_sync(0xFFFFFFFFu, s, o);
        q += __shfl_down_sync(0xFFFFFFFFu, q, o);
    }
    __shared__ float ss[8], sq[8];
    const int w = threadIdx.x >> 5, lane = threadIdx.x & 31;
    if (lane == 0) { ss[w] = s; sq[w] = q; }
    __syncthreads();
    if (w == 0) {
        s = (lane < 8) ? ss[lane] : 0.f;
        q = (lane < 8) ? sq[lane] : 0.f;
        #pragma unroll
        for (int o = 4; o; o >>= 1) {
            s += __shfl_down_sync(0xFFFFFFFFu, s, o);
            q += __shfl_down_sync(0xFFFFFFFFu, q, o);
        }
        if (lane == 0) { g_ps[r] = s; g_pq[r] = q; }
    }
}

// ---------------------------------------------------------------------------
// Kernel 2: per-channel threshold (gamma > 0 guaranteed)
// ---------------------------------------------------------------------------
__global__ void k_stats2(const float* __restrict__ gamma,
                         const float* __restrict__ beta) {
    const int c = blockIdx.x;
    const int n = threadIdx.x;
    float s = g_ps[n * C_ + c];
    float q = g_pq[n * C_ + c];
    #pragma unroll
    for (int o = 16; o; o >>= 1) {
        s += __shfl_down_sync(0xFFFFFFFFu, s, o);
        q += __shfl_down_sync(0xFFFFFFFFu, q, o);
    }
    __shared__ float s1, q1;
    if (threadIdx.x == 32) { s1 = s; q1 = q; }
    __syncthreads();
    if (threadIdx.x == 0) {
        s += s1; q += q1;
        const float invn = 1.f / ((float)N_ * (float)L_);
        float mean = s * invn;
        float var  = fmaf(-mean, mean, q * invn);
        float inv  = rsqrtf(var + 1e-5f);
        g_thresh[c] = mean - beta[c] / (inv * gamma[c]);
    }
}

// ---------------------------------------------------------------------------
// Kernel 3: binarize to transposed packed bits [n][w][c]
// grid = (64 wgroups, 64 n), block = 256 = (4 wi, 64 c)
// warp: 8 channels x 4 words -> reads 128B/thread coalesced,
// writes 32B-contiguous sectors (8 consecutive c per wi)
// ---------------------------------------------------------------------------
__global__ void k_binarize(const float* __restrict__ I) {
    const int n  = blockIdx.y;
    const int c  = threadIdx.x >> 2;
    const int wi = threadIdx.x & 3;
    const int w  = blockIdx.x * 4 + wi;
    const float t = g_thresh[c];
    const float4* p = reinterpret_cast<const float4*>(
        I + ((size_t)(n * C_ + c)) * L_ + w * 32);
    unsigned b = 0;
    #pragma unroll
    for (int i = 0; i < 8; i++) {
        float4 v = p[i];
        b |= (v.x >= t ? 1u : 0u) << (i * 4 + 0);
        b |= (v.y >= t ? 1u : 0u) << (i * 4 + 1);
        b |= (v.z >= t ? 1u : 0u) << (i * 4 + 2);
        b |= (v.w >= t ? 1u : 0u) << (i * 4 + 3);
    }
    g_bits[(size_t)n * (LW_ * C_) + w * C_ + c] = b;
}

// ---------------------------------------------------------------------------
// Kernel 3b: weights f32 -> fp16, layout [k][oc][c]
// ---------------------------------------------------------------------------
__global__ void k_wf16(const float* __restrict__ W) {
    const int idx = blockIdx.x * 512 + threadIdx.x;   // 57344 total
    const int oc = idx / (C_ * K_);
    const int r  = idx - oc * (C_ * K_);
    const int c  = r / K_;
    const int k  = r - c * K_;
    g_wf16[(k * O_ + oc) * C_ + c] = __float2half_rn(W[idx]);
}

// ---------------------------------------------------------------------------
// Kernel 4: HMMA conv (7 shifted GEMM passes) + alpha + maxpool2
// grid = (32 pos-tiles, 2 oc-blocks, 64 n), block = 256 (8 warps)
// Block out tile: [64 oc x 256 pos]; warp tile 64 oc x 32 pos.
// smem (99.8 KB -> 2 blocks/SM):
//   A_k [64 oc][64 c] fp16, k=0..6, pitch 144B  @ 0      (7 * 9216)
//   B^T [262 rows][64 c] fp16, pitch 144B       @ 64512  (37728)
// For tap k: D[oc][p] += A_k[oc][:] . B^T[p + k][:]
// ---------------------------------------------------------------------------
#define PT     256
#define APITCH 144
#define AK_SZ  (64 * APITCH)           // 9216
#define SM_B   (7 * AK_SZ)             // 64512
#define SM_TOT (SM_B + 262 * APITCH)   // 102240

__global__ void __launch_bounds__(256, 2)
k_conv_mma(const float* __restrict__ alpha,
           float* __restrict__ out) {
    extern __shared__ char sm[];
    const uint32_t smb = smem_u32(sm);
    const int tid  = threadIdx.x;
    const int wid  = tid >> 5;
    const int lane = tid & 31;
    const int l0  = blockIdx.x * PT;
    const int ocb = blockIdx.y;            // 0/1 -> oc base ocb*64
    const int n   = blockIdx.z;

    // --- A fill: plain uint4 copy from precomputed g_wf16
    {
        const uint4* src = reinterpret_cast<const uint4*>(g_wf16);
        // global row (k*128 + ocb*64 + oc) has 8 uint4s
        for (int i = tid; i < 7 * 64 * 8; i += 256) {
            int kk = i >> 9;               // /512
            int r  = i & 511;
            int oc = r >> 3;
            int j  = r & 7;
            uint4 v = src[(kk * O_ + ocb * 64 + oc) * 8 + j];
            *reinterpret_cast<uint4*>(sm + kk * AK_SZ + oc * APITCH + j * 16) = v;
        }
    }
    // --- B decode: row r = position l0-3+r, 64 channels fp16
    {
        const uint4* bb = reinterpret_cast<const uint4*>(
            g_bits + (size_t)n * (LW_ * C_));
        for (int r = tid; r < 262; r += 256) {
            const int pos = l0 - 3 + r;
            char* row = sm + SM_B + r * APITCH;
            if (pos >= 0 && pos < L_) {
                const int widx = pos >> 5, bit = pos & 31;
                const uint4* wrow = bb + widx * 16;   // 64 words for this w
                #pragma unroll
                for (int g = 0; g < 8; g++) {         // channels g*8..g*8+7
                    uint4 w0 = wrow[g * 2 + 0];       // c = g*8 .. +3
                    uint4 w1 = wrow[g * 2 + 1];       // c = g*8+4 .. +7
                    const unsigned* ws = &w0.x;
                    uint32_t h4[4];
                    #pragma unroll
                    for (int j = 0; j < 4; j++) {
                        unsigned a = (j < 2) ? ((j == 0) ? w0.x : w0.z)
                                             : ((j == 2) ? w1.x : w1.z);
                        unsigned bws = (j < 2) ? ((j == 0) ? w0.y : w0.w)
                                               : ((j == 2) ? w1.y : w1.w);
                        uint32_t hlo = ((a   >> bit) & 1u) ? 0x3C00u : 0xBC00u;
                        uint32_t hhi = ((bws >> bit) & 1u) ? 0x3C00u : 0xBC00u;
                        h4[j] = hlo | (hhi << 16);
                    }
                    (void)ws;
                    uint4 v; v.x = h4[0]; v.y = h4[1]; v.z = h4[2]; v.w = h4[3];
                    *reinterpret_cast<uint4*>(row + g * 16) = v;
                }
            } else {
                #pragma unroll
                for (int g = 0; g < 8; g++) {
                    uint4 z; z.x = z.y = z.z = z.w = 0u;
                    *reinterpret_cast<uint4*>(row + g * 16) = z;
                }
            }
        }
    }
    __syncthreads();

    // --- mainloop: warp tile 64 oc x 32 pos
    const int n0w = wid * 32;

    float acc[4][4][4];
    #pragma unroll
    for (int mi = 0; mi < 4; mi++)
        #pragma unroll
        for (int ni = 0; ni < 4; ni++)
            #pragma unroll
            for (int j = 0; j < 4; j++) acc[mi][ni][j] = 0.f;

    const uint32_t a_lane = (uint32_t)((lane & 15) * APITCH + (lane >> 4) * 16);
    const uint32_t b_lane = (uint32_t)((lane & 7)  * APITCH + ((lane >> 3) & 1) * 16);
    const uint32_t a_base = smb + a_lane;
    const uint32_t b_base = smb + SM_B + n0w * APITCH + b_lane;

    #pragma unroll
    for (int k = 0; k < K_; k++) {
        const uint32_t ab  = a_base + k * AK_SZ;
        const uint32_t bbk = b_base + k * APITCH;     // tap shift = +1 row
        #pragma unroll
        for (int ks = 0; ks < 4; ks++) {              // c in steps of 16
            uint32_t a[4][4];
            #pragma unroll
            for (int mi = 0; mi < 4; mi++)
                ldsm_x4(a[mi], ab + mi * (16 * APITCH) + ks * 32);
            uint32_t b[4][2];
            #pragma unroll
            for (int ni = 0; ni < 4; ni++)
                ldsm_x2(b[ni], bbk + ni * (8 * APITCH) + ks * 32);
            #pragma unroll
            for (int mi = 0; mi < 4; mi++)
                #pragma unroll
                for (int ni = 0; ni < 4; ni++)
                    mma16816(acc[mi][ni], a[mi], b[ni]);
        }
    }

    // --- epilogue: maxpool2 + alpha in registers, direct STG
    const int lr = lane >> 2;     // 0..7
    const int lc = lane & 3;      // 0..3
    const int pbase = (l0 >> 1) + (n0w >> 1);
    #pragma unroll
    for (int mi = 0; mi < 4; mi++) {
        const int oc0 = ocb * 64 + mi * 16 + lr;
        const int oc1 = oc0 + 8;
        const float a0 = alpha[oc0];
        const float a1 = alpha[oc1];
        float* r0 = out + ((size_t)(n * O_ + oc0)) * LOUT_ + pbase;
        float* r1 = out + ((size_t)(n * O_ + oc1)) * LOUT_ + pbase;
        #pragma unroll
        for (int ni = 0; ni < 4; ni++) {
            const int pp = ni * 4 + lc;
            r0[pp] = fmaxf(acc[mi][ni][0], acc[mi][ni][1]) * a0;
            r1[pp] = fmaxf(acc[mi][ni][2], acc[mi][ni][3]) * a1;
        }
    }
}

// ---------------------------------------------------------------------------
extern "C" void kernel_launch(void* const* d_in, const int* in_sizes, int n_in,
                              void* d_out, int out_size) {
    const float* I     = (const float*)d_in[0];
    const float* gamma = (const float*)d_in[1];
    const float* beta  = (const float*)d_in[2];
    const float* W     = (const float*)d_in[3];
    const float* alpha = (const float*)d_in[4];
    float* out = (float*)d_out;

    k_wf16<<<112, 512>>>(W);
    k_stats1<<<N_ * C_, 256>>>(I);
    k_stats2<<<C_, 64>>>(gamma, beta);
    {
        dim3 g(LW_ / 4, N_);
        k_binarize<<<g, 256>>>(I);
    }

    cudaFuncSetAttribute(k_conv_mma,
                         cudaFuncAttributeMaxDynamicSharedMemorySize, SM_TOT);
    dim3 grid(L_ / PT, 2, N_);   // (32, 2, 64)
    k_conv_mma<<<grid, 256, SM_TOT>>>(alpha, out);
}

// round 16
// speedup vs baseline: 8.0732x; 1.0825x over previous
#include <cuda_runtime.h>
#include <cuda_fp16.h>
#include <cstdint>

// Problem constants
//   I     [64, 64, 8192] f32
//   gamma [64], beta [64]
//   W     [128, 64, 7]
//   alpha [128, 1]
//   out   [64, 128, 4096] f32
#define N_  64
#define C_  64
#define L_  8192
#define O_  128
#define K_  7
#define LOUT_ 4096
#define LW_  256          // words per (n,c) row = L/32

// Scratch (device globals; no allocations allowed)
__device__ float    g_ps[N_ * C_];
__device__ float    g_pq[N_ * C_];
__device__ float    g_thresh[C_];
// bits transposed: [n][word w][channel c]
__device__ unsigned g_bits[N_ * LW_ * C_ + 16];
// fp16 weights: [k][oc][c]
__device__ __align__(16) __half g_wf16[K_ * O_ * C_];

// ====================== baseline-PTX warp MMA helpers ======================
__device__ __forceinline__ uint32_t smem_u32(const void* p) {
    uint32_t a;
    asm("{ .reg .u64 t; cvta.to.shared.u64 t, %1; cvt.u32.u64 %0, t; }"
        : "=r"(a) : "l"(p));
    return a;
}
__device__ __forceinline__ void ldsm_x4(uint32_t* r, uint32_t addr) {
    asm volatile("ldmatrix.sync.aligned.m8n8.x4.shared.b16 {%0,%1,%2,%3}, [%4];"
                 : "=r"(r[0]), "=r"(r[1]), "=r"(r[2]), "=r"(r[3]) : "r"(addr));
}
__device__ __forceinline__ void mma16816(float* d, const uint32_t* a,
                                         const uint32_t* b) {
    asm volatile(
        "mma.sync.aligned.m16n8k16.row.col.f32.f16.f16.f32 "
        "{%0,%1,%2,%3}, {%4,%5,%6,%7}, {%8,%9}, {%0,%1,%2,%3};"
        : "+f"(d[0]), "+f"(d[1]), "+f"(d[2]), "+f"(d[3])
        : "r"(a[0]), "r"(a[1]), "r"(a[2]), "r"(a[3]), "r"(b[0]), "r"(b[1]));
}

// ---------------------------------------------------------------------------
// Kernel 1: per-(n,c) row reduction
// ---------------------------------------------------------------------------
__global__ void k_stats1(const float* __restrict__ I) {
    const int r = blockIdx.x;
    const float4* p = reinterpret_cast<const float4*>(I + (size_t)r * L_);
    float s = 0.f, q = 0.f;
    #pragma unroll 4
    for (int i = threadIdx.x; i < L_ / 4; i += 256) {
        float4 v = p[i];
        s += v.x + v.y + v.z + v.w;
        q += v.x * v.x + v.y * v.y + v.z * v.z + v.w * v.w;
    }
    #pragma unroll
    for (int o = 16; o; o >>= 1) {
        s += __shfl_down_sync(0xFFFFFFFFu, s, o);
        q += __shfl_down_sync(0xFFFFFFFFu, q, o);
    }
    __shared__ float ss[8], sq[8];
    const int w = threadIdx.x >> 5, lane = threadIdx.x & 31;
    if (lane == 0) { ss[w] = s; sq[w] = q; }
    __syncthreads();
    if (w == 0) {
        s = (lane < 8) ? ss[lane] : 0.f;
        q = (lane < 8) ? sq[lane] : 0.f;
        #pragma unroll
        for (int o = 4; o; o >>= 1) {
            s += __shfl_down_sync(0xFFFFFFFFu, s, o);
            q += __shfl_down_sync(0xFFFFFFFFu, q, o);
        }
        if (lane == 0) { g_ps[r] = s; g_pq[r] = q; }
    }
}

// ---------------------------------------------------------------------------
// Kernel 2: per-channel threshold (gamma > 0 guaranteed)
// ---------------------------------------------------------------------------
__global__ void k_stats2(const float* __restrict__ gamma,
                         const float* __restrict__ beta) {
    const int c = blockIdx.x;
    const int n = threadIdx.x;
    float s = g_ps[n * C_ + c];
    float q = g_pq[n * C_ + c];
    #pragma unroll
    for (int o = 16; o; o >>= 1) {
        s += __shfl_down_sync(0xFFFFFFFFu, s, o);
        q += __shfl_down_sync(0xFFFFFFFFu, q, o);
    }
    __shared__ float s1, q1;
    if (threadIdx.x == 32) { s1 = s; q1 = q; }
    __syncthreads();
    if (threadIdx.x == 0) {
        s += s1; q += q1;
        const float invn = 1.f / ((float)N_ * (float)L_);
        float mean = s * invn;
        float var  = fmaf(-mean, mean, q * invn);
        float inv  = rsqrtf(var + 1e-5f);
        g_thresh[c] = mean - beta[c] / (inv * gamma[c]);
    }
}

// ---------------------------------------------------------------------------
// Kernel 3: binarize to transposed packed bits [n][w][c]
// ---------------------------------------------------------------------------
__global__ void k_binarize(const float* __restrict__ I) {
    const int n  = blockIdx.y;
    const int c  = threadIdx.x >> 2;
    const int wi = threadIdx.x & 3;
    const int w  = blockIdx.x * 4 + wi;
    const float t = g_thresh[c];
    const float4* p = reinterpret_cast<const float4*>(
        I + ((size_t)(n * C_ + c)) * L_ + w * 32);
    unsigned b = 0;
    #pragma unroll
    for (int i = 0; i < 8; i++) {
        float4 v = p[i];
        b |= (v.x >= t ? 1u : 0u) << (i * 4 + 0);
        b |= (v.y >= t ? 1u : 0u) << (i * 4 + 1);
        b |= (v.z >= t ? 1u : 0u) << (i * 4 + 2);
        b |= (v.w >= t ? 1u : 0u) << (i * 4 + 3);
    }
    g_bits[(size_t)n * (LW_ * C_) + w * C_ + c] = b;
}

// ---------------------------------------------------------------------------
// Kernel 3b: weights f32 -> fp16, layout [k][oc][c]
// ---------------------------------------------------------------------------
__global__ void k_wf16(const float* __restrict__ W) {
    const int idx = blockIdx.x * 512 + threadIdx.x;   // 57344 total
    const int oc = idx / (C_ * K_);
    const int r  = idx - oc * (C_ * K_);
    const int c  = r / K_;
    const int k  = r - c * K_;
    g_wf16[(k * O_ + oc) * C_ + c] = __float2half_rn(W[idx]);
}

// ---------------------------------------------------------------------------
// Kernel 4: HMMA conv (7 shifted GEMM passes) + alpha + maxpool2
// grid = (32 pos-tiles, 2 oc-blocks, 64 n), block = 128 (4 warps)
// Block out tile: [64 oc x 256 pos]; warp tile 64 oc x 64 pos.
// smem (99.8 KB -> 2 blocks/SM):
//   A_k [64 oc][64 c] fp16, k=0..6, pitch 144B  @ 0      (7 * 9216)
//   B^T [262 rows][64 c] fp16, pitch 144B       @ 64512
// Per c16-chunk: 4 ldsm_x4 (A, 4 mi) + 4 ldsm_x4 (B, 8 ni, 2 per ldsm)
// -> 32 mma  (8 mma / KB of LDS traffic; 2x round-15 ratio)
// ---------------------------------------------------------------------------
#define PT     256
#define APITCH 144
#define AK_SZ  (64 * APITCH)           // 9216
#define SM_B   (7 * AK_SZ)             // 64512
#define SM_TOT (SM_B + 262 * APITCH)   // 102240

__global__ void __launch_bounds__(128, 2)
k_conv_mma(const float* __restrict__ alpha,
           float* __restrict__ out) {
    extern __shared__ char sm[];
    const uint32_t smb = smem_u32(sm);
    const int tid  = threadIdx.x;
    const int wid  = tid >> 5;
    const int lane = tid & 31;
    const int l0  = blockIdx.x * PT;
    const int ocb = blockIdx.y;            // 0/1 -> oc base ocb*64
    const int n   = blockIdx.z;

    // --- A fill: plain uint4 copy from precomputed g_wf16
    {
        const uint4* src = reinterpret_cast<const uint4*>(g_wf16);
        for (int i = tid; i < 7 * 64 * 8; i += 128) {
            int kk = i >> 9;
            int r  = i & 511;
            int oc = r >> 3;
            int j  = r & 7;
            uint4 v = src[(kk * O_ + ocb * 64 + oc) * 8 + j];
            *reinterpret_cast<uint4*>(sm + kk * AK_SZ + oc * APITCH + j * 16) = v;
        }
    }
    // --- B decode: row r = position l0-3+r, 64 channels fp16
    {
        const uint4* bb = reinterpret_cast<const uint4*>(
            g_bits + (size_t)n * (LW_ * C_));
        for (int r = tid; r < 262; r += 128) {
            const int pos = l0 - 3 + r;
            char* row = sm + SM_B + r * APITCH;
            if (pos >= 0 && pos < L_) {
                const int widx = pos >> 5, bit = pos & 31;
                const uint4* wrow = bb + widx * 16;   // 64 words for this w
                #pragma unroll
                for (int g = 0; g < 8; g++) {         // channels g*8..g*8+7
                    uint4 w0 = wrow[g * 2 + 0];
                    uint4 w1 = wrow[g * 2 + 1];
                    uint32_t h4[4];
                    h4[0] = (((w0.x >> bit) & 1u) ? 0x3C00u : 0xBC00u)
                          | ((((w0.y >> bit) & 1u) ? 0x3C00u : 0xBC00u) << 16);
                    h4[1] = (((w0.z >> bit) & 1u) ? 0x3C00u : 0xBC00u)
                          | ((((w0.w >> bit) & 1u) ? 0x3C00u : 0xBC00u) << 16);
                    h4[2] = (((w1.x >> bit) & 1u) ? 0x3C00u : 0xBC00u)
                          | ((((w1.y >> bit) & 1u) ? 0x3C00u : 0xBC00u) << 16);
                    h4[3] = (((w1.z >> bit) & 1u) ? 0x3C00u : 0xBC00u)
                          | ((((w1.w >> bit) & 1u) ? 0x3C00u : 0xBC00u) << 16);
                    uint4 v; v.x = h4[0]; v.y = h4[1]; v.z = h4[2]; v.w = h4[3];
                    *reinterpret_cast<uint4*>(row + g * 16) = v;
                }
            } else {
                #pragma unroll
                for (int g = 0; g < 8; g++) {
                    uint4 z; z.x = z.y = z.z = z.w = 0u;
                    *reinterpret_cast<uint4*>(row + g * 16) = z;
                }
            }
        }
    }
    __syncthreads();

    // --- mainloop: warp tile 64 oc x 64 pos
    const int n0w = wid * 64;

    float acc[4][8][4];
    #pragma unroll
    for (int mi = 0; mi < 4; mi++)
        #pragma unroll
        for (int ni = 0; ni < 8; ni++)
            #pragma unroll
            for (int j = 0; j < 4; j++) acc[mi][ni][j] = 0.f;

    // A ldsm_x4: rows (lane&15), col16 = lane>>4  -> one 16x16 tile (1 mi)
    const uint32_t a_lane = (uint32_t)((lane & 15) * APITCH + (lane >> 4) * 16);
    // B ldsm_x4: 16 rows, two 8-row fragments (2 ni):
    //   row = (lane&7) + 8*(lane>>4), col16 = (lane>>3)&1
    const uint32_t b_lane = (uint32_t)(((lane & 7) + ((lane >> 4) << 3)) * APITCH
                                       + ((lane >> 3) & 1) * 16);
    const uint32_t a_base = smb + a_lane;
    const uint32_t b_base = smb + SM_B + n0w * APITCH + b_lane;

    #pragma unroll
    for (int k = 0; k < K_; k++) {
        const uint32_t ab  = a_base + k * AK_SZ;
        const uint32_t bbk = b_base + k * APITCH;     // tap shift = +1 row
        #pragma unroll
        for (int ks = 0; ks < 4; ks++) {              // c in steps of 16
            uint32_t a[4][4];
            #pragma unroll
            for (int mi = 0; mi < 4; mi++)
                ldsm_x4(a[mi], ab + mi * (16 * APITCH) + ks * 32);
            uint32_t b[4][4];                          // [pair][4] -> ni=2*pair{+1}
            #pragma unroll
            for (int pr = 0; pr < 4; pr++)
                ldsm_x4(b[pr], bbk + pr * (16 * APITCH) + ks * 32);
            #pragma unroll
            for (int mi = 0; mi < 4; mi++)
                #pragma unroll
                for (int pr = 0; pr < 4; pr++) {
                    mma16816(acc[mi][2 * pr + 0], a[mi], &b[pr][0]);
                    mma16816(acc[mi][2 * pr + 1], a[mi], &b[pr][2]);
                }
        }
    }

    // --- epilogue: maxpool2 + alpha in registers, direct STG
    const int lr = lane >> 2;     // 0..7
    const int lc = lane & 3;      // 0..3
    const int pbase = (l0 >> 1) + (n0w >> 1);
    #pragma unroll
    for (int mi = 0; mi < 4; mi++) {
        const int oc0 = ocb * 64 + mi * 16 + lr;
        const int oc1 = oc0 + 8;
        const float a0 = alpha[oc0];
        const float a1 = alpha[oc1];
        float* r0 = out + ((size_t)(n * O_ + oc0)) * LOUT_ + pbase;
        float* r1 = out + ((size_t)(n * O_ + oc1)) * LOUT_ + pbase;
        #pragma unroll
        for (int ni = 0; ni < 8; ni++) {
            const int pp = ni * 4 + lc;
            r0[pp] = fmaxf(acc[mi][ni][0], acc[mi][ni][1]) * a0;
            r1[pp] = fmaxf(acc[mi][ni][2], acc[mi][ni][3]) * a1;
        }
    }
}

// ---------------------------------------------------------------------------
extern "C" void kernel_launch(void* const* d_in, const int* in_sizes, int n_in,
                              void* d_out, int out_size) {
    const float* I     = (const float*)d_in[0];
    const float* gamma = (const float*)d_in[1];
    const float* beta  = (const float*)d_in[2];
    const float* W     = (const float*)d_in[3];
    const float* alpha = (const float*)d_in[4];
    float* out = (float*)d_out;

    k_wf16<<<112, 512>>>(W);
    k_stats1<<<N_ * C_, 256>>>(I);
    k_stats2<<<C_, 64>>>(gamma, beta);
    {
        dim3 g(LW_ / 4, N_);
        k_binarize<<<g, 256>>>(I);
    }

    cudaFuncSetAttribute(k_conv_mma,
                         cudaFuncAttributeMaxDynamicSharedMemorySize, SM_TOT);
    dim3 grid(L_ / PT, 2, N_);   // (32, 2, 64)
    k_conv_mma<<<grid, 128, SM_TOT>>>(alpha, out);
}

// round 17
// speedup vs baseline: 8.1061x; 1.0041x over previous
#include <cuda_runtime.h>
#include <cuda_fp16.h>
#include <cstdint>

// Problem constants
//   I     [64, 64, 8192] f32
//   gamma [64], beta [64]
//   W     [128, 64, 7]
//   alpha [128, 1]
//   out   [64, 128, 4096] f32
#define N_  64
#define C_  64
#define L_  8192
#define O_  128
#define K_  7
#define LOUT_ 4096
#define LW_  256          // 32-bit words per (n,c) row = L/32

// Scratch (device globals; no allocations allowed)
__device__ float    g_ps[N_ * C_];
__device__ float    g_pq[N_ * C_];
__device__ float    g_thresh[C_];
// bit-transposed signs: g_bitsT[n*L + l] = 64-bit channel mask at position l
// (.x = channels 0..31, .y = channels 32..63; bit c = sign(I) >= thresh)
__device__ uint2    g_bitsT[N_ * L_];
// fp16 weights: [k][oc][c]
__device__ __align__(16) __half g_wf16[K_ * O_ * C_];

// ====================== baseline-PTX warp MMA helpers ======================
__device__ __forceinline__ uint32_t smem_u32(const void* p) {
    uint32_t a;
    asm("{ .reg .u64 t; cvta.to.shared.u64 t, %1; cvt.u32.u64 %0, t; }"
        : "=r"(a) : "l"(p));
    return a;
}
__device__ __forceinline__ void ldsm_x4(uint32_t* r, uint32_t addr) {
    asm volatile("ldmatrix.sync.aligned.m8n8.x4.shared.b16 {%0,%1,%2,%3}, [%4];"
                 : "=r"(r[0]), "=r"(r[1]), "=r"(r[2]), "=r"(r[3]) : "r"(addr));
}
__device__ __forceinline__ void mma16816(float* d, const uint32_t* a,
                                         const uint32_t* b) {
    asm volatile(
        "mma.sync.aligned.m16n8k16.row.col.f32.f16.f16.f32 "
        "{%0,%1,%2,%3}, {%4,%5,%6,%7}, {%8,%9}, {%0,%1,%2,%3};"
        : "+f"(d[0]), "+f"(d[1]), "+f"(d[2]), "+f"(d[3])
        : "r"(a[0]), "r"(a[1]), "r"(a[2]), "r"(a[3]), "r"(b[0]), "r"(b[1]));
}

// ---------------------------------------------------------------------------
// Kernel 1: per-(n,c) row reduction
// ---------------------------------------------------------------------------
__global__ void k_stats1(const float* __restrict__ I) {
    const int r = blockIdx.x;
    const float4* p = reinterpret_cast<const float4*>(I + (size_t)r * L_);
    float s = 0.f, q = 0.f;
    #pragma unroll 4
    for (int i = threadIdx.x; i < L_ / 4; i += 256) {
        float4 v = p[i];
        s += v.x + v.y + v.z + v.w;
        q += v.x * v.x + v.y * v.y + v.z * v.z + v.w * v.w;
    }
    #pragma unroll
    for (int o = 16; o; o >>= 1) {
        s += __shfl_down_sync(0xFFFFFFFFu, s, o);
        q += __shfl_down_sync(0xFFFFFFFFu, q, o);
    }
    __shared__ float ss[8], sq[8];
    const int w = threadIdx.x >> 5, lane = threadIdx.x & 31;
    if (lane == 0) { ss[w] = s; sq[w] = q; }
    __syncthreads();
    if (w == 0) {
        s = (lane < 8) ? ss[lane] : 0.f;
        q = (lane < 8) ? sq[lane] : 0.f;
        #pragma unroll
        for (int o = 4; o; o >>= 1) {
            s += __shfl_down_sync(0xFFFFFFFFu, s, o);
            q += __shfl_down_sync(0xFFFFFFFFu, q, o);
        }
        if (lane == 0) { g_ps[r] = s; g_pq[r] = q; }
    }
}

// ---------------------------------------------------------------------------
// Kernel 2: per-channel threshold (gamma > 0 guaranteed)
// ---------------------------------------------------------------------------
__global__ void k_stats2(const float* __restrict__ gamma,
                         const float* __restrict__ beta) {
    const int c = blockIdx.x;
    const int n = threadIdx.x;
    float s = g_ps[n * C_ + c];
    float q = g_pq[n * C_ + c];
    #pragma unroll
    for (int o = 16; o; o >>= 1) {
        s += __shfl_down_sync(0xFFFFFFFFu, s, o);
        q += __shfl_down_sync(0xFFFFFFFFu, q, o);
    }
    __shared__ float s1, q1;
    if (threadIdx.x == 32) { s1 = s; q1 = q; }
    __syncthreads();
    if (threadIdx.x == 0) {
        s += s1; q += q1;
        const float invn = 1.f / ((float)N_ * (float)L_);
        float mean = s * invn;
        float var  = fmaf(-mean, mean, q * invn);
        float inv  = rsqrtf(var + 1e-5f);
        g_thresh[c] = mean - beta[c] / (inv * gamma[c]);
    }
}

// ---------------------------------------------------------------------------
// Kernel 3: binarize + warp ballot bit-transpose -> g_bitsT[n][l]
// grid = (LW/4, N), block = 256 (8 warps)
// warp (wid): word w = bx*4 + (wid>>1), channel half = wid&1, lane -> c
// ---------------------------------------------------------------------------
__global__ void k_binarize(const float* __restrict__ I) {
    const int n    = blockIdx.y;
    const int wid  = threadIdx.x >> 5;
    const int lane = threadIdx.x & 31;
    const int w    = blockIdx.x * 4 + (wid >> 1);
    const int half = wid & 1;
    const int c    = half * 32 + lane;
    const float t  = g_thresh[c];
    const float4* p = reinterpret_cast<const float4*>(
        I + ((size_t)(n * C_ + c)) * L_ + w * 32);
    unsigned b = 0;
    #pragma unroll
    for (int i = 0; i < 8; i++) {
        float4 v = p[i];
        b |= (v.x >= t ? 1u : 0u) << (i * 4 + 0);
        b |= (v.y >= t ? 1u : 0u) << (i * 4 + 1);
        b |= (v.z >= t ? 1u : 0u) << (i * 4 + 2);
        b |= (v.w >= t ? 1u : 0u) << (i * 4 + 3);
    }
    // transpose: bit pp of my word -> bit (lane) of mask for position w*32+pp
    unsigned mymask = 0;
    #pragma unroll
    for (int pp = 0; pp < 32; pp++) {
        unsigned m = __ballot_sync(0xFFFFFFFFu, (b >> pp) & 1u);
        if (lane == pp) mymask = m;
    }
    const int l = w * 32 + lane;
    reinterpret_cast<unsigned*>(g_bitsT)[((size_t)n * L_ + l) * 2 + half] = mymask;
}

// ---------------------------------------------------------------------------
// Kernel 3b: weights f32 -> fp16, layout [k][oc][c]
// ---------------------------------------------------------------------------
__global__ void k_wf16(const float* __restrict__ W) {
    const int idx = blockIdx.x * 512 + threadIdx.x;   // 57344 total
    const int oc = idx / (C_ * K_);
    const int r  = idx - oc * (C_ * K_);
    const int c  = r / K_;
    const int k  = r - c * K_;
    g_wf16[(k * O_ + oc) * C_ + c] = __float2half_rn(W[idx]);
}

// ---------------------------------------------------------------------------
// Kernel 4: HMMA conv (7 shifted GEMM passes) + alpha + maxpool2
// grid = (32 pos-tiles, 2 oc-blocks, 64 n), block = 128 (4 warps)
// Block out tile: [64 oc x 256 pos]; warp tile 64 oc x 64 pos.
// smem (103.8 KB -> 2 blocks/SM):
//   LUT [256] uint4: byte -> 8 fp16 signs     @ 0       (4096)
//   A_k [64 oc][64 c] fp16, k=0..6, pitch 144 @ 4096    (7 * 9216)
//   B^T [262 rows][64 c] fp16, pitch 144      @ 68608   (37728)
// B decode per row: 1 LDG.64 mask + 8 LUT LDS.128 + 8 STS.128 (~41 instr,
// was ~280 with bit-by-bit expansion)
// ---------------------------------------------------------------------------
#define PT     256
#define APITCH 144
#define AK_SZ  (64 * APITCH)           // 9216
#define SM_LUT 0
#define SM_A   4096
#define SM_B   (SM_A + 7 * AK_SZ)      // 68608
#define SM_TOT (SM_B + 262 * APITCH)   // 106336

__global__ void __launch_bounds__(128, 2)
k_conv_mma(const float* __restrict__ alpha,
           float* __restrict__ out) {
    extern __shared__ char sm[];
    const uint32_t smb = smem_u32(sm);
    const int tid  = threadIdx.x;
    const int wid  = tid >> 5;
    const int lane = tid & 31;
    const int l0  = blockIdx.x * PT;
    const int ocb = blockIdx.y;            // 0/1 -> oc base ocb*64
    const int n   = blockIdx.z;

    // --- build sign LUT: byte -> 8 fp16 (+1/-1)
    {
        uint4* lut = reinterpret_cast<uint4*>(sm + SM_LUT);
        #pragma unroll
        for (int e = tid; e < 256; e += 128) {
            uint32_t h[4];
            #pragma unroll
            for (int j = 0; j < 4; j++) {
                uint32_t lo = ((e >> (2 * j))     & 1u) ? 0x3C00u : 0xBC00u;
                uint32_t hi = ((e >> (2 * j + 1)) & 1u) ? 0x3C00u : 0xBC00u;
                h[j] = lo | (hi << 16);
            }
            uint4 v; v.x = h[0]; v.y = h[1]; v.z = h[2]; v.w = h[3];
            lut[e] = v;
        }
    }
    __syncthreads();

    // --- A fill: plain uint4 copy from precomputed g_wf16
    {
        const uint4* src = reinterpret_cast<const uint4*>(g_wf16);
        for (int i = tid; i < 7 * 64 * 8; i += 128) {
            int kk = i >> 9;
            int r  = i & 511;
            int oc = r >> 3;
            int j  = r & 7;
            uint4 v = src[(kk * O_ + ocb * 64 + oc) * 8 + j];
            *reinterpret_cast<uint4*>(sm + SM_A + kk * AK_SZ + oc * APITCH
                                      + j * 16) = v;
        }
    }
    // --- B decode via LUT: row r = position l0-3+r
    {
        const uint4* lut = reinterpret_cast<const uint4*>(sm + SM_LUT);
        for (int r = tid; r < 262; r += 128) {
            const int pos = l0 - 3 + r;
            char* row = sm + SM_B + r * APITCH;
            if (pos >= 0 && pos < L_) {
                uint2 m = g_bitsT[(size_t)n * L_ + pos];
                #pragma unroll
                for (int g = 0; g < 4; g++) {
                    *reinterpret_cast<uint4*>(row + g * 16) =
                        lut[(m.x >> (g * 8)) & 255u];
                }
                #pragma unroll
                for (int g = 0; g < 4; g++) {
                    *reinterpret_cast<uint4*>(row + 64 + g * 16) =
                        lut[(m.y >> (g * 8)) & 255u];
                }
            } else {
                #pragma unroll
                for (int g = 0; g < 8; g++) {
                    uint4 z; z.x = z.y = z.z = z.w = 0u;
                    *reinterpret_cast<uint4*>(row + g * 16) = z;
                }
            }
        }
    }
    __syncthreads();

    // --- mainloop: warp tile 64 oc x 64 pos
    const int n0w = wid * 64;

    float acc[4][8][4];
    #pragma unroll
    for (int mi = 0; mi < 4; mi++)
        #pragma unroll
        for (int ni = 0; ni < 8; ni++)
            #pragma unroll
            for (int j = 0; j < 4; j++) acc[mi][ni][j] = 0.f;

    const uint32_t a_lane = (uint32_t)((lane & 15) * APITCH + (lane >> 4) * 16);
    const uint32_t b_lane = (uint32_t)(((lane & 7) + ((lane >> 4) << 3)) * APITCH
                                       + ((lane >> 3) & 1) * 16);
    const uint32_t a_base = smb + SM_A + a_lane;
    const uint32_t b_base = smb + SM_B + n0w * APITCH + b_lane;

    #pragma unroll
    for (int k = 0; k < K_; k++) {
        const uint32_t ab  = a_base + k * AK_SZ;
        const uint32_t bbk = b_base + k * APITCH;     // tap shift = +1 row
        #pragma unroll
        for (int ks = 0; ks < 4; ks++) {              // c in steps of 16
            uint32_t a[4][4];
            #pragma unroll
            for (int mi = 0; mi < 4; mi++)
                ldsm_x4(a[mi], ab + mi * (16 * APITCH) + ks * 32);
            uint32_t b[4][4];                          // [pair] -> ni=2*pair{+1}
            #pragma unroll
            for (int pr = 0; pr < 4; pr++)
                ldsm_x4(b[pr], bbk + pr * (16 * APITCH) + ks * 32);
            #pragma unroll
            for (int mi = 0; mi < 4; mi++)
                #pragma unroll
                for (int pr = 0; pr < 4; pr++) {
                    mma16816(acc[mi][2 * pr + 0], a[mi], &b[pr][0]);
                    mma16816(acc[mi][2 * pr + 1], a[mi], &b[pr][2]);
                }
        }
    }

    // --- epilogue: maxpool2 + alpha in registers, direct STG
    const int lr = lane >> 2;     // 0..7
    const int lc = lane & 3;      // 0..3
    const int pbase = (l0 >> 1) + (n0w >> 1);
    #pragma unroll
    for (int mi = 0; mi < 4; mi++) {
        const int oc0 = ocb * 64 + mi * 16 + lr;
        const int oc1 = oc0 + 8;
        const float a0 = alpha[oc0];
        const float a1 = alpha[oc1];
        float* r0 = out + ((size_t)(n * O_ + oc0)) * LOUT_ + pbase;
        float* r1 = out + ((size_t)(n * O_ + oc1)) * LOUT_ + pbase;
        #pragma unroll
        for (int ni = 0; ni < 8; ni++) {
            const int pp = ni * 4 + lc;
            r0[pp] = fmaxf(acc[mi][ni][0], acc[mi][ni][1]) * a0;
            r1[pp] = fmaxf(acc[mi][ni][2], acc[mi][ni][3]) * a1;
        }
    }
}

// ---------------------------------------------------------------------------
extern "C" void kernel_launch(void* const* d_in, const int* in_sizes, int n_in,
                              void* d_out, int out_size) {
    const float* I     = (const float*)d_in[0];
    const float* gamma = (const float*)d_in[1];
    const float* beta  = (const float*)d_in[2];
    const float* W     = (const float*)d_in[3];
    const float* alpha = (const float*)d_in[4];
    float* out = (float*)d_out;

    k_wf16<<<112, 512>>>(W);
    k_stats1<<<N_ * C_, 256>>>(I);
    k_stats2<<<C_, 64>>>(gamma, beta);
    {
        dim3 g(LW_ / 4, N_);
        k_binarize<<<g, 256>>>(I);
    }

    cudaFuncSetAttribute(k_conv_mma,
                         cudaFuncAttributeMaxDynamicSharedMemorySize, SM_TOT);
    dim3 grid(L_ / PT, 2, N_);   // (32, 2, 64)
    k_conv_mma<<<grid, 128, SM_TOT>>>(alpha, out);
}